// round 13
// baseline (speedup 1.0000x reference)
#include <cuda_runtime.h>
#include <math.h>
#include <stdint.h>

#define BB 4
#define NN 100000
#define KK 16
#define NPAIR (NN / 2)
#define NQUAD (NN / 4)         // 25000 quad-row groups per batch
#define EPSF 1e-6f
#define W_CE 2.0f
#define W_DICE 0.1f

#define GX 111                 // blocks per batch (444 total = 3/SM)
#define NBLK (GX * BB)
#define NWPB 8
#define NWARP (GX * NWPB)      // 888 warps per batch
#define ENT 544                // padded slot; real: 256 D | 256 INTER | 16 S1M
#define NE_REAL 528
#define NE_TOT (BB * NE_REAL)  // 2112

#define TOTROWS (BB * NN)      // 400000
#define C1_BLOCKS 296
#define C1_WARPS (C1_BLOCKS * 8)   // 2368
#define C1_ITERS (TOTROWS / 32)    // 12500 exact

struct Part { float e[ENT]; };
__device__ Part g_part[NBLK];
__device__ int g_count;                       // self-resetting
__device__ unsigned char g_vlab[TOTROWS];     // label per row (rewritten每 launch)

// ---------------------------------------------------------------------------
__device__ __forceinline__ unsigned long long pack_dup(float x) {
    unsigned long long r;
    unsigned int u = __float_as_uint(x);
    asm("mov.b64 %0, {%1, %1};" : "=l"(r) : "r"(u));
    return r;
}
__device__ __forceinline__ void fma2(unsigned long long& acc,
                                     unsigned long long a,
                                     unsigned long long b) {
    asm("fma.rn.f32x2 %0, %1, %2, %0;" : "+l"(acc) : "l"(a), "l"(b));
}
__device__ __forceinline__ float lo32(unsigned long long x) {
    return __uint_as_float((unsigned int)(x & 0xffffffffULL));
}
__device__ __forceinline__ float hi32(unsigned long long x) {
    return __uint_as_float((unsigned int)(x >> 32));
}

// ---------------------------------------------------------------------------
// Kernel 1: label compressor. Warp-iter: 16 coalesced 128B loads (2 rows
// each), ballot+ffs argmax, 32B label store. Pure streaming shape.
// ---------------------------------------------------------------------------
__global__ void __launch_bounds__(256, 3) compress_kernel(
    const float* __restrict__ gt) {
    const int lane = threadIdx.x & 31;
    const int gw = (blockIdx.x * blockDim.x + threadIdx.x) >> 5;
    const unsigned FULL = 0xffffffffu;

    for (int it = gw; it < C1_ITERS; it += C1_WARPS) {
        const int base = it * 32;                 // 32 rows
        const float* src = gt + (size_t)base * KK;

        float vv[16];
#pragma unroll
        for (int s = 0; s < 16; s++) vv[s] = __ldg(src + s * 32 + lane);

        unsigned int packed = 0;
#pragma unroll
        for (int s = 0; s < 16; s++) {
            unsigned bal = __ballot_sync(FULL, vv[s] > 0.5f);
            int lab0 = __ffs(bal & 0xffffu) - 1;
            int lab1 = __ffs(bal >> 16) - 1;
            if (lane == s) packed = (unsigned)(lab0 | (lab1 << 8));
        }
        if (lane < 16)
            *(unsigned short*)(g_vlab + base + 2 * lane) = (unsigned short)packed;
    }
}

// ---------------------------------------------------------------------------
// Kernel 2: fused mainloop + epilogue. gt replaced by labels; one-hot
// synthesized in registers. 2 pairs (4 rows) per warp-iter, 4 loads total.
// ---------------------------------------------------------------------------
__global__ void __launch_bounds__(256, 3) fused_kernel(
    const float* __restrict__ mask,
    const float* __restrict__ valid,
    float* __restrict__ out) {
    __shared__ float pti[NWPB][ENT];
    __shared__ float v1m[NWPB][32];
    __shared__ float facc[NE_TOT];
    __shared__ float cost[BB][KK][KK];
    __shared__ float mS1M[BB][KK], mSUMM[BB][KK], mSUMG[BB][KK], mV[BB];
    __shared__ int colmap[BB][KK];
    __shared__ float rce[BB * KK], rdice[BB * KK];
    __shared__ int is_last;

    const int b = blockIdx.y;
    const int bx = blockIdx.x;
    const int t = threadIdx.x;
    const int lane = t & 31;
    const int w = t >> 5;
    const int i = lane & 15;   // cost-row index owned by this lane
    const int jh = lane >> 4;  // row-of-pair owned; j-half owned
    const unsigned FULL = 0xffffffffu;
    const int gwarp = bx * NWPB + w;

    const float* mask_b = mask + (size_t)b * NN * KK;
    const float* val_b = valid + (size_t)b * NN;
    const unsigned char* vlab_b = g_vlab + (size_t)b * NN;

    unsigned long long aD[4], aI[4];
#pragma unroll
    for (int k = 0; k < 4; k++) { aD[k] = 0ull; aI[k] = 0ull; }
    float s1m = 0.0f;   // accumulates +v*log2(1-m); negated at writeback

    const int jb4 = jh * 4;   // my u64-slot base in label>>1 space

#pragma unroll 2
    for (int q = gwarp; q < NQUAD; q += NWARP) {
        // rows 4q .. 4q+3 : pair A = rows (4q, 4q+1), pair B = (4q+2, 4q+3)
        const size_t ro = (size_t)q * 64;
        float mA = __ldg(mask_b + ro + lane);         // row 4q+jh, col i
        float mB = __ldg(mask_b + ro + 32 + lane);    // row 4q+2+jh, col i
        uchar4 vl = *(const uchar4*)(vlab_b + 4 * q); // broadcast
        float4 v4 = *(const float4*)(val_b + 4 * q);  // broadcast

        // ---- pair A ----
        {
            float vown = jh ? v4.y : v4.x;
            int labown = jh ? vl.y : vl.x;
            int laboth = jh ? vl.x : vl.y;
            float l1 = __log2f(mA);
            float l2 = __log2f(1.0f - mA);
            float down = vown * (l2 - l1);
            float rown = vown * mA;
            s1m = fmaf(vown, l2, s1m);
            float doth = __shfl_xor_sync(FULL, down, 16);
            float roth = __shfl_xor_sync(FULL, rown, 16);

            unsigned long long bown =
                0x3f800000ull << ((labown & 1) << 5);
            unsigned long long both =
                0x3f800000ull << ((laboth & 1) << 5);
            int iown = (labown >> 1) - jb4;
            int ioth = (laboth >> 1) - jb4;
            unsigned long long Dw = pack_dup(down), Rw = pack_dup(rown);
            unsigned long long Dx = pack_dup(doth), Rx = pack_dup(roth);
#pragma unroll
            for (int k = 0; k < 4; k++) {
                unsigned long long g_o = (iown == k) ? bown : 0ull;
                unsigned long long g_x = (ioth == k) ? both : 0ull;
                fma2(aD[k], Dw, g_o);
                fma2(aI[k], Rw, g_o);
                fma2(aD[k], Dx, g_x);
                fma2(aI[k], Rx, g_x);
            }
        }
        // ---- pair B ----
        {
            float vown = jh ? v4.w : v4.z;
            int labown = jh ? vl.w : vl.z;
            int laboth = jh ? vl.z : vl.w;
            float l1 = __log2f(mB);
            float l2 = __log2f(1.0f - mB);
            float down = vown * (l2 - l1);
            float rown = vown * mB;
            s1m = fmaf(vown, l2, s1m);
            float doth = __shfl_xor_sync(FULL, down, 16);
            float roth = __shfl_xor_sync(FULL, rown, 16);

            unsigned long long bown =
                0x3f800000ull << ((labown & 1) << 5);
            unsigned long long both =
                0x3f800000ull << ((laboth & 1) << 5);
            int iown = (labown >> 1) - jb4;
            int ioth = (laboth >> 1) - jb4;
            unsigned long long Dw = pack_dup(down), Rw = pack_dup(rown);
            unsigned long long Dx = pack_dup(doth), Rx = pack_dup(roth);
#pragma unroll
            for (int k = 0; k < 4; k++) {
                unsigned long long g_o = (iown == k) ? bown : 0ull;
                unsigned long long g_x = (ioth == k) ? both : 0ull;
                fma2(aD[k], Dw, g_o);
                fma2(aI[k], Rw, g_o);
                fma2(aD[k], Dx, g_x);
                fma2(aI[k], Rx, g_x);
            }
        }
    }

    // ---- per-warp -> shared ----
    v1m[w][lane] = s1m;
    {
        const int basej = i * 16 + jh * 8;
#pragma unroll
        for (int k = 0; k < 4; k++) {
            pti[w][basej + 2 * k] = lo32(aD[k]);
            pti[w][basej + 2 * k + 1] = hi32(aD[k]);
            pti[w][256 + basej + 2 * k] = lo32(aI[k]);
            pti[w][256 + basej + 2 * k + 1] = hi32(aI[k]);
        }
    }
    __syncthreads();

    // ---- block reduce -> deterministic per-block partial slot ----
    Part* gp = &g_part[b * GX + bx];
#pragma unroll
    for (int e0 = 0; e0 < 512; e0 += 256) {
        int e = e0 + t;
        float sum = 0.0f;
#pragma unroll
        for (int ww = 0; ww < NWPB; ww++) sum += pti[ww][e];
        gp->e[e] = sum;
    }
    if (t < 16) {
        float sum = 0.0f;
#pragma unroll
        for (int ww = 0; ww < NWPB; ww++) sum += v1m[ww][t] + v1m[ww][t + 16];
        gp->e[512 + t] = -sum;   // S1M = -sum(v*log2(1-m))
    }

    __threadfence();
    __syncthreads();
    if (t == 0) {
        int old = atomicAdd(&g_count, 1);
        is_last = (old == NBLK - 1);
    }
    __syncthreads();
    if (!is_last) return;

    if (t == 0) g_count = 0;

    // ---- final reduce: 9 entries per thread, jammed for MLP ----
    {
        float sacc[9];
        const float* bas[9];
        int ok[9];
#pragma unroll
        for (int k = 0; k < 9; k++) {
            int q = t + k * 256;
            ok[k] = (q < NE_TOT);
            sacc[k] = 0.0f;
            if (ok[k]) {
                int bb2 = q / NE_REAL;
                int e = q - bb2 * NE_REAL;
                bas[k] = &g_part[bb2 * GX].e[e];
            } else {
                bas[k] = &g_part[0].e[0];
            }
        }
        for (int gx = 0; gx < GX; gx++) {
#pragma unroll
            for (int k = 0; k < 9; k++)
                if (ok[k]) sacc[k] += bas[k][(size_t)gx * ENT];
        }
#pragma unroll
        for (int k = 0; k < 9; k++) {
            int q = t + k * 256;
            if (ok[k]) facc[q] = sacc[k];
        }
    }
    __syncthreads();

    // ---- marginals from INTER (+ direct S1M) ----
    if (t < BB * KK) {
        int bb2 = t / KK, q = t % KK;
        const float* F = facc + bb2 * NE_REAL;
        float summ = 0.0f, sumg = 0.0f;
#pragma unroll
        for (int x = 0; x < KK; x++) {
            summ += F[256 + q * 16 + x];
            sumg += F[256 + x * 16 + q];
        }
        mS1M[bb2][q] = F[512 + q];
        mSUMM[bb2][q] = summ;
        mSUMG[bb2][q] = sumg;
    }
    __syncthreads();
    if (t < BB) {
        float v = 0.0f;
#pragma unroll
        for (int x = 0; x < KK; x++) v += mSUMG[t][x];
        mV[t] = v;
    }
    __syncthreads();

    // ---- cost matrices ----
    const float LN2 = 0.69314718055994530942f;
    for (int idx = t; idx < BB * 256; idx += 256) {
        int bb2 = idx >> 8;
        int r = idx & 255;
        int ii = r >> 4, jj = r & 15;
        const float* F = facc + bb2 * NE_REAL;
        float denom = fmaxf(mV[bb2], 1.0f);
        float ce = LN2 * (F[ii * 16 + jj] + mS1M[bb2][ii]) / denom;
        float dice = 1.0f - 2.0f * F[256 + ii * 16 + jj] /
                                (mSUMM[bb2][ii] + mSUMG[bb2][jj] + EPSF);
        cost[bb2][ii][jj] = W_CE * ce + W_DICE * dice;
    }
    __syncthreads();

    // ---- warp-parallel Hungarian (JV), one warp per batch ----
    if (w < BB) {
        const int bb2 = w;
        float ur = 0.0f;
        float vv = 0.0f;
        int pcol = 0;

        for (int ii = 1; ii <= KK; ii++) {
            if (lane == 0) pcol = ii;
            float minv = 1e30f;
            int way = 0;
            int used = 0;
            int rowcov = 0;
            int j0 = 0;

            while (true) {
                if (lane == j0) used = 1;
                int i0 = __shfl_sync(FULL, pcol, j0);
                if (lane == i0) rowcov = 1;
                float u_i0 = __shfl_sync(FULL, ur, i0);

                int active = (lane >= 1 && lane <= KK && !used);
                if (active) {
                    float c = cost[bb2][i0 - 1][lane - 1];
                    float cur = c - u_i0 - vv;
                    if (cur < minv) { minv = cur; way = j0; }
                }
                float val = active ? minv : 1e30f;
                float red = val;
#pragma unroll
                for (int off = 16; off; off >>= 1)
                    red = fminf(red, __shfl_xor_sync(FULL, red, off));
                unsigned bal = __ballot_sync(FULL, val == red);
                int j1 = __ffs(bal) - 1;
                float delta = red;

                if (rowcov) ur += delta;
                if (used) vv -= delta;
                else if (lane >= 1 && lane <= KK) minv -= delta;

                j0 = j1;
                int pj = __shfl_sync(FULL, pcol, j0);
                if (pj == 0) break;
            }
            while (j0 != 0) {
                int j1 = __shfl_sync(FULL, way, j0);
                int pv = __shfl_sync(FULL, pcol, j1);
                if (lane == j0) pcol = pv;
                j0 = j1;
            }
        }
        if (lane >= 1 && lane <= KK) colmap[bb2][pcol - 1] = lane - 1;
    }
    __syncthreads();

    // ---- loss ----
    if (t < BB * KK) {
        int bb2 = t / KK, ii = t % KK;
        int jj = colmap[bb2][ii];
        const float* F = facc + bb2 * NE_REAL;
        rce[t] = LN2 * (F[ii * 16 + jj] + mS1M[bb2][ii]);
        rdice[t] = 1.0f - 2.0f * F[256 + ii * 16 + jj] /
                              (mSUMM[bb2][ii] + mSUMG[bb2][jj] + EPSF);
    }
    __syncthreads();

    if (t == 0) {
        float cs = 0.0f, ds = 0.0f, vt = 0.0f;
        for (int x = 0; x < BB * KK; x++) { cs += rce[x]; ds += rdice[x]; }
        for (int bb2 = 0; bb2 < BB; bb2++) vt += mV[bb2];
        float l_ce = cs / (fmaxf(vt, 1.0f) * (float)KK);
        float l_dice = ds / (float)(BB * KK);
        out[0] = W_CE * l_ce + W_DICE * l_dice;
    }
}

// ---------------------------------------------------------------------------
extern "C" void kernel_launch(void* const* d_in, const int* in_sizes, int n_in,
                              void* d_out, int out_size) {
    const float* mask = (const float*)d_in[0];
    const float* gt = (const float*)d_in[1];
    const float* valid = (const float*)d_in[2];
    float* out = (float*)d_out;

    compress_kernel<<<C1_BLOCKS, 256>>>(gt);
    dim3 grid(GX, BB);
    fused_kernel<<<grid, 256>>>(mask, valid, out);
}